// round 1
// baseline (speedup 1.0000x reference)
#include <cuda_runtime.h>
#include <math.h>

#define B_    256
#define M_    64
#define DSLOT 126
#define D_    128
#define C_    62
#define KP_   32
#define NCOL  (C_*KP_)   // 1984
#define BETA_ 4.0f
#define XYW_  0.5f
#define TOPP_ 0.9f

// Survivor threshold: a column (c,k) can contribute a nonzero fp32 sim only if
// exp(-4*dist2) >= 2^-149, i.e. dist2 < 26. Since dist2 >= (||c||-||f||)^2 and
// ||f|| <= sqrt(1.25)+eps < 1.13, any column with ||c||^2 >= 40 yields
// (||c||-1.13)^2 >= (6.324-1.13)^2 = 26.98 > 26 -> sim == 0.0f exactly for all
// (b,m), matching the fp32 reference bit-for-bit on those terms.
#define C2_SURV 40.0f

__device__ int            g_nsurv;
__device__ int            g_surv[NCOL];
__device__ float          g_w[NCOL];
__device__ float          g_feat[B_*M_*D_];
__device__ float          g_scores[B_*C_];
__device__ float          g_kcnt[B_];
__device__ unsigned char  g_active[B_*M_];

// --- Kernel 1: top-p selection per batch -> k and active set (order-free) ---
// scores sums slot_score over the set {order[i] : i < k}; summation order is
// irrelevant, so we only need the membership mask in original index space:
// active[m] <=> rank(m) < k under stable descending sort.
__global__ void k_topp(const float* __restrict__ P, const float* __restrict__ mask)
{
    int b = blockIdx.x;
    int m = threadIdx.x;
    if (b == 0 && m == 0) g_nsurv = 0;   // reset compaction counter (stream-ordered before k_prep)

    __shared__ float v[M_];
    __shared__ float vs[M_];
    __shared__ int   ksh;

    float val = P[b*M_ + m] * mask[b*M_ + m];
    v[m] = val;
    __syncthreads();

    int rank = 0;
    float tot = 0.f;
    #pragma unroll
    for (int j = 0; j < M_; j++) {
        float o = v[j];
        tot += o;
        if (o > val || (o == val && j < m)) rank++;   // stable descending
    }
    vs[rank] = val;
    __syncthreads();

    if (m == 0) {
        float thr = TOPP_ * (tot + 1e-8f);
        float cs = 0.f;
        int k = 0;
        #pragma unroll
        for (int j = 0; j < M_; j++) {
            cs += vs[j];
            if (cs <= thr) k++;
        }
        if (k < 1) k = 1;
        ksh = k;
        g_kcnt[b] = (float)k;
    }
    __syncthreads();
    g_active[b*M_ + m] = (rank < ksh) ? 1 : 0;
}

// --- Kernel 2: zero scores, softmax(psi), per-column ||c||^2 + survivor compaction ---
__global__ void k_prep(const float* __restrict__ centers, const float* __restrict__ psi)
{
    int tid = blockIdx.x * blockDim.x + threadIdx.x;
    int nthreads = gridDim.x * blockDim.x;

    for (int i = tid; i < B_*C_; i += nthreads) g_scores[i] = 0.f;

    if (tid < C_) {  // softmax over K per class (only used on the survivor path)
        int c = tid;
        float mx = -1e30f;
        #pragma unroll
        for (int k = 0; k < KP_; k++) mx = fmaxf(mx, psi[c*KP_ + k]);
        float e[KP_];
        float s = 0.f;
        #pragma unroll
        for (int k = 0; k < KP_; k++) { e[k] = expf(psi[c*KP_ + k] - mx); s += e[k]; }
        float inv = 1.f / s;
        #pragma unroll
        for (int k = 0; k < KP_; k++) g_w[c*KP_ + k] = e[k] * inv;
    }

    // warp per column: ||c||^2, compact survivors
    int warp = tid >> 5;
    int lane = tid & 31;
    int nwarps = nthreads >> 5;
    for (int col = warp; col < NCOL; col += nwarps) {
        const float* cp = centers + col * D_;
        float s = 0.f;
        #pragma unroll
        for (int dd = lane; dd < D_; dd += 32) { float x = cp[dd]; s += x * x; }
        #pragma unroll
        for (int off = 16; off; off >>= 1) s += __shfl_xor_sync(0xffffffffu, s, off);
        if (lane == 0 && s < C2_SURV) {
            int idx = atomicAdd(&g_nsurv, 1);
            g_surv[idx] = col;
        }
    }
}

// --- Kernel 3: feature build (only if any column survived the norm bound) ---
__global__ void k_feat(const float* __restrict__ S, const float* __restrict__ XY)
{
    if (g_nsurv == 0) return;
    int b = blockIdx.x, m = threadIdx.x;
    const float* s = S + (size_t)(b*M_ + m) * DSLOT;
    float n = 0.f;
    for (int dd = 0; dd < DSLOT; dd++) { float x = s[dd]; n += x * x; }
    float inv = 1.f / fmaxf(sqrtf(n), 1e-12f);
    float* f = g_feat + (size_t)(b*M_ + m) * D_;
    for (int dd = 0; dd < DSLOT; dd++) f[dd] = s[dd] * inv;
    float x0 = XY[(b*M_ + m)*2 + 0];
    float x1 = XY[(b*M_ + m)*2 + 1];
    float invx = XYW_ / fmaxf(sqrtf(x0*x0 + x1*x1), 1e-12f);
    f[DSLOT + 0] = x0 * invx;
    f[DSLOT + 1] = x1 * invx;
}

// --- Kernel 4: survivor scoring (dot/dist2/exp/weighted accumulate) ---
__global__ void k_score(const float* __restrict__ centers)
{
    int ns = g_nsurv;
    if (ns == 0) return;
    int b = blockIdx.x;
    for (int t = threadIdx.x; t < ns * M_; t += blockDim.x) {
        int si = t / M_;
        int m  = t % M_;
        if (!g_active[b*M_ + m]) continue;
        int col = g_surv[si];
        int c = col >> 5;  // col / KP_ (KP_=32)
        const float* f  = g_feat + (size_t)(b*M_ + m) * D_;
        const float* ce = centers + (size_t)col * D_;
        float dot = 0.f, f2 = 0.f, c2 = 0.f;
        #pragma unroll 8
        for (int dd = 0; dd < D_; dd++) {
            float a = f[dd], bb = ce[dd];
            dot += a * bb; f2 += a * a; c2 += bb * bb;
        }
        float dist2 = f2 + c2 - 2.f * dot;
        float sim = expf(-BETA_ * dist2);
        atomicAdd(&g_scores[b*C_ + c], sim * g_w[col]);
    }
}

// --- Kernel 5: out = alpha*base + (1-alpha)*scores/k ---
__global__ void k_final(const float* __restrict__ base, const float* __restrict__ alpha_p,
                        float* __restrict__ out)
{
    int i = blockIdx.x * blockDim.x + threadIdx.x;
    if (i >= B_*C_) return;
    float alpha = 1.f / (1.f + expf(-alpha_p[0]));
    int b = i / C_;
    out[i] = alpha * base[i] + (1.f - alpha) * (g_scores[i] / g_kcnt[b]);
}

extern "C" void kernel_launch(void* const* d_in, const int* in_sizes, int n_in,
                              void* d_out, int out_size)
{
    const float* base = (const float*)d_in[0];  // (B, C)
    const float* S    = (const float*)d_in[1];  // (B, M, 126)
    const float* XY   = (const float*)d_in[2];  // (B, M, 2)
    const float* P    = (const float*)d_in[3];  // (B, M)
    const float* mask = (const float*)d_in[4];  // (B, M)
    const float* cen  = (const float*)d_in[5];  // (C, K, 128)
    const float* psi  = (const float*)d_in[6];  // (C, K)
    const float* ap   = (const float*)d_in[7];  // scalar
    float* out = (float*)d_out;                 // (B, C) float32

    k_topp <<<B_, M_>>>(P, mask);
    k_prep <<<248, 256>>>(cen, psi);
    k_feat <<<B_, M_>>>(S, XY);
    k_score<<<B_, 256>>>(cen);
    k_final<<<(B_*C_ + 255)/256, 256>>>(base, ap, out);
}

// round 2
// speedup vs baseline: 2.2802x; 2.2802x over previous
#include <cuda_runtime.h>
#include <math.h>

#define B_    256
#define M_    64
#define DSLOT 126
#define D_    128
#define C_    62
#define KP_   32
#define BETA_ 4.0f
#define XYW_  0.5f
#define TOPP_ 0.9f

// A column (c,k) can contribute a nonzero fp32 sim only if exp(-4*dist2) >= 2^-149,
// i.e. dist2 < 26. Since dist2 >= (||c||-||f||)^2 and ||f|| <= sqrt(1.25)+eps < 1.13,
// ||c||^2 >= 40 gives (6.324-1.13)^2 = 26.98 > 26 -> sim == 0.0f exactly for every
// (b,m), identical to the fp32 reference. So if no column of class c survives,
// scores[:,c] == 0 exactly and out[:,c] = alpha*base[:,c].
#define C2_SURV 40.0f

#define NTHREADS 512

__global__ __launch_bounds__(NTHREADS)
void k_fused(const float* __restrict__ base, const float* __restrict__ S,
             const float* __restrict__ XY, const float* __restrict__ P,
             const float* __restrict__ mask, const float* __restrict__ cen,
             const float* __restrict__ psi, const float* __restrict__ ap,
             float* __restrict__ out)
{
    const int c    = blockIdx.x;           // one block per class
    const int tid  = threadIdx.x;
    const int warp = tid >> 5;
    const int lane = tid & 31;

    __shared__ float sh_c2[KP_];
    __shared__ int   sh_ns;
    if (tid == 0) sh_ns = 0;
    __syncthreads();

    // ||center||^2 for this class's 32 columns; 16 warps -> warp w does cols w, w+16
    for (int k = warp; k < KP_; k += (NTHREADS >> 5)) {
        const float* cp = cen + (size_t)(c * KP_ + k) * D_;
        float s = 0.f;
        #pragma unroll
        for (int dd = lane; dd < D_; dd += 32) { float x = cp[dd]; s += x * x; }
        #pragma unroll
        for (int off = 16; off; off >>= 1) s += __shfl_xor_sync(0xffffffffu, s, off);
        if (lane == 0) {
            sh_c2[k] = s;
            if (s < C2_SURV) atomicAdd(&sh_ns, 1);
        }
    }
    __syncthreads();

    const float alpha = 1.f / (1.f + expf(-ap[0]));

    if (sh_ns == 0) {
        // Fast path: every sim term for class c underflows to exactly 0.0f.
        for (int b = tid; b < B_; b += NTHREADS)
            out[b * C_ + c] = alpha * base[b * C_ + c];
        return;
    }

    // ---------------- survivor fallback (correct; normally never taken) ----------------
    __shared__ float sh_w[KP_];          // softmax(psi[c,:])
    __shared__ float sh_v[M_], sh_vs[M_];
    __shared__ unsigned char sh_act[M_];
    __shared__ int   sh_k;
    __shared__ float sh_score;

    if (tid == 0) {
        float mx = -1e30f;
        #pragma unroll
        for (int k = 0; k < KP_; k++) mx = fmaxf(mx, psi[c * KP_ + k]);
        float e[KP_], s = 0.f;
        #pragma unroll
        for (int k = 0; k < KP_; k++) { e[k] = expf(psi[c * KP_ + k] - mx); s += e[k]; }
        float inv = 1.f / s;
        #pragma unroll
        for (int k = 0; k < KP_; k++) sh_w[k] = e[k] * inv;
    }
    __syncthreads();

    for (int b = 0; b < B_; b++) {
        // --- top-p: k and active set for batch b (threads 0..63) ---
        if (tid < M_) {
            int m = tid;
            float val = P[b * M_ + m] * mask[b * M_ + m];
            sh_v[m] = val;
            __syncwarp();                     // warps 0,1 each hold half of sh_v
        }
        __syncthreads();
        if (tid < M_) {
            int m = tid;
            float val = sh_v[m];
            int rank = 0; float tot = 0.f;
            #pragma unroll
            for (int j = 0; j < M_; j++) {
                float o = sh_v[j];
                tot += o;
                if (o > val || (o == val && j < m)) rank++;   // stable descending
            }
            sh_vs[rank] = val;
            __syncthreads();
            if (m == 0) {
                float thr = TOPP_ * (tot + 1e-8f);
                float cs = 0.f; int kk = 0;
                #pragma unroll
                for (int j = 0; j < M_; j++) { cs += sh_vs[j]; if (cs <= thr) kk++; }
                if (kk < 1) kk = 1;
                sh_k = kk;
                sh_score = 0.f;
            }
            __syncthreads();
            sh_act[m] = (rank < sh_k) ? 1 : 0;
        } else {
            __syncthreads();  // match the __syncthreads inside the tid<M_ branch
            __syncthreads();
        }
        __syncthreads();

        // --- accumulate sum over (active m) x (surviving cols) of sim * w ---
        float acc = 0.f;
        for (int pr = tid; pr < M_ * KP_; pr += NTHREADS) {
            int m = pr >> 5;
            int k = pr & 31;
            if (!sh_act[m] || sh_c2[k] >= C2_SURV) continue;

            const float* srow = S + ((size_t)b * M_ + m) * DSLOT;
            float n = 0.f;
            for (int dd = 0; dd < DSLOT; dd++) { float x = srow[dd]; n += x * x; }
            float invs = 1.f / fmaxf(sqrtf(n), 1e-12f);
            float x0 = XY[(b * M_ + m) * 2 + 0];
            float x1 = XY[(b * M_ + m) * 2 + 1];
            float invx = XYW_ / fmaxf(sqrtf(x0 * x0 + x1 * x1), 1e-12f);

            const float* cp = cen + (size_t)(c * KP_ + k) * D_;
            float dot = 0.f, f2 = 0.f;
            for (int dd = 0; dd < DSLOT; dd++) {
                float fv = srow[dd] * invs;
                dot += fv * cp[dd]; f2 += fv * fv;
            }
            float fx0 = x0 * invx, fx1 = x1 * invx;
            dot += fx0 * cp[DSLOT] + fx1 * cp[DSLOT + 1];
            f2  += fx0 * fx0 + fx1 * fx1;

            float dist2 = f2 + sh_c2[k] - 2.f * dot;
            acc += expf(-BETA_ * dist2) * sh_w[k];
        }
        atomicAdd(&sh_score, acc);
        __syncthreads();
        if (tid == 0)
            out[b * C_ + c] = alpha * base[b * C_ + c]
                            + (1.f - alpha) * sh_score / (float)sh_k;
        __syncthreads();
    }
}

extern "C" void kernel_launch(void* const* d_in, const int* in_sizes, int n_in,
                              void* d_out, int out_size)
{
    const float* base = (const float*)d_in[0];  // (B, C)
    const float* S    = (const float*)d_in[1];  // (B, M, 126)
    const float* XY   = (const float*)d_in[2];  // (B, M, 2)
    const float* P    = (const float*)d_in[3];  // (B, M)
    const float* mask = (const float*)d_in[4];  // (B, M)
    const float* cen  = (const float*)d_in[5];  // (C, K, 128)
    const float* psi  = (const float*)d_in[6];  // (C, K)
    const float* ap   = (const float*)d_in[7];  // scalar
    float* out = (float*)d_out;                 // (B, C) float32

    k_fused<<<C_, NTHREADS>>>(base, S, XY, P, mask, cen, psi, ap, out);
}